// round 1
// baseline (speedup 1.0000x reference)
#include <cuda_runtime.h>
#include <cstdint>

// Problem constants: B=512, T=256, C=384, HS=16
#define TT   256
#define CC   384
#define HSZ  16
#define NQKV 48          // q|k|v concatenated columns
#define KCH  16          // K-chunk for projection
#define SBLK 32          // attention column block
#define XPAD 17          // padded row stride for q/k/v/x tiles
#define SPAD 33          // padded row stride for S block

// smem plan (floats):
//  phase1: xs_hi[256*17] xs_lo[256*17] ws_hi[16*48] ws_lo[16*48]  = 10240 f
//  phase2: q[256*17] k[256*17] v[256*17] s[256*33] pmax[256] psum[256] rinv[32]
//        = 3*4352 + 8448 + 544 = 22048 f = 88192 B   (max)
#define SMEM_FLOATS (3 * TT * XPAD + TT * SPAD + 256 + 256 + 32)
#define SMEM_BYTES  (SMEM_FLOATS * 4)

__device__ __forceinline__ unsigned f2tf(float f) {
    unsigned r;
    asm("cvt.rna.tf32.f32 %0, %1;" : "=r"(r) : "f"(f));
    return r;
}

__device__ __forceinline__ void mma_tf32(float* c, const unsigned* a, const unsigned* b) {
    asm volatile(
        "mma.sync.aligned.m16n8k8.row.col.f32.tf32.tf32.f32 "
        "{%0,%1,%2,%3}, {%4,%5,%6,%7}, {%8,%9}, {%0,%1,%2,%3};"
        : "+f"(c[0]), "+f"(c[1]), "+f"(c[2]), "+f"(c[3])
        : "r"(a[0]), "r"(a[1]), "r"(a[2]), "r"(a[3]), "r"(b[0]), "r"(b[1]));
}

__global__ void __launch_bounds__(256, 2) head_fused_kernel(
    const float* __restrict__ x,
    const float* __restrict__ wk,
    const float* __restrict__ wq,
    const float* __restrict__ wv,
    float* __restrict__ out)
{
    extern __shared__ float sm[];
    const int b    = blockIdx.x;
    const int tid  = threadIdx.x;
    const int lane = tid & 31;
    const int warp = tid >> 5;
    const int grp  = lane >> 2;  // 0..7
    const int tig  = lane & 3;   // 0..3
    const int R    = warp * 32;  // this warp's 32 rows

    // ---- phase-1 smem views ----
    float* xs_hi = sm;
    float* xs_lo = xs_hi + TT * XPAD;
    float* ws_hi = xs_lo + TT * XPAD;
    float* ws_lo = ws_hi + KCH * NQKV;
    // ---- phase-2 smem views (overlap phase 1) ----
    float* q_s   = sm;
    float* k_s   = q_s + TT * XPAD;
    float* v_s   = k_s + TT * XPAD;
    float* s_blk = v_s + TT * XPAD;
    float* pmax  = s_blk + TT * SPAD;
    float* psum  = pmax + 256;
    float* rinv  = psum + 256;

    const float* xb = x + (size_t)b * TT * CC;

    // ================= Phase 1: qkv = x @ [Wq|Wk|Wv], split-tf32 =================
    float acc[2][6][4];
#pragma unroll
    for (int mt = 0; mt < 2; ++mt)
#pragma unroll
        for (int nt = 0; nt < 6; ++nt)
#pragma unroll
            for (int e = 0; e < 4; ++e) acc[mt][nt][e] = 0.f;

    for (int kc = 0; kc < CC / KCH; ++kc) {
        // load x chunk [256][16], coalesced float4, split hi/lo
#pragma unroll
        for (int i = 0; i < 4; ++i) {
            int row = (tid >> 2) + i * 64;
            int seg = (tid & 3) * 4;
            float4 v4 = *reinterpret_cast<const float4*>(xb + row * CC + kc * KCH + seg);
            float vv[4] = {v4.x, v4.y, v4.z, v4.w};
#pragma unroll
            for (int j = 0; j < 4; ++j) {
                unsigned h = f2tf(vv[j]);
                xs_hi[row * XPAD + seg + j] = __uint_as_float(h);
                xs_lo[row * XPAD + seg + j] =
                    __uint_as_float(f2tf(vv[j] - __uint_as_float(h)));
            }
        }
        // load W chunk [16][48]: cols 0-15 = Wq, 16-31 = Wk, 32-47 = Wv
        for (int idx = tid; idx < KCH * NQKV; idx += 256) {
            int kk = idx / NQKV, j = idx % NQKV;
            int gk = kc * KCH + kk;
            float w = (j < 16) ? wq[gk * HSZ + j]
                    : (j < 32) ? wk[gk * HSZ + (j - 16)]
                               : wv[gk * HSZ + (j - 32)];
            unsigned h = f2tf(w);
            ws_hi[idx] = __uint_as_float(h);
            ws_lo[idx] = __uint_as_float(f2tf(w - __uint_as_float(h)));
        }
        __syncthreads();

#pragma unroll
        for (int k8 = 0; k8 < 2; ++k8) {
            const int ko = k8 * 8;
            unsigned ah[2][4], al[2][4];
#pragma unroll
            for (int mt = 0; mt < 2; ++mt) {
                int r0 = R + mt * 16 + grp;
                ah[mt][0] = __float_as_uint(xs_hi[r0 * XPAD + ko + tig]);
                ah[mt][1] = __float_as_uint(xs_hi[(r0 + 8) * XPAD + ko + tig]);
                ah[mt][2] = __float_as_uint(xs_hi[r0 * XPAD + ko + tig + 4]);
                ah[mt][3] = __float_as_uint(xs_hi[(r0 + 8) * XPAD + ko + tig + 4]);
                al[mt][0] = __float_as_uint(xs_lo[r0 * XPAD + ko + tig]);
                al[mt][1] = __float_as_uint(xs_lo[(r0 + 8) * XPAD + ko + tig]);
                al[mt][2] = __float_as_uint(xs_lo[r0 * XPAD + ko + tig + 4]);
                al[mt][3] = __float_as_uint(xs_lo[(r0 + 8) * XPAD + ko + tig + 4]);
            }
#pragma unroll
            for (int nt = 0; nt < 6; ++nt) {
                int cb = nt * 8 + grp;
                unsigned bh[2], bl[2];
                bh[0] = __float_as_uint(ws_hi[(ko + tig) * NQKV + cb]);
                bh[1] = __float_as_uint(ws_hi[(ko + tig + 4) * NQKV + cb]);
                bl[0] = __float_as_uint(ws_lo[(ko + tig) * NQKV + cb]);
                bl[1] = __float_as_uint(ws_lo[(ko + tig + 4) * NQKV + cb]);
#pragma unroll
                for (int mt = 0; mt < 2; ++mt) {
                    mma_tf32(acc[mt][nt], ah[mt], bh);
                    mma_tf32(acc[mt][nt], ah[mt], bl);
                    mma_tf32(acc[mt][nt], al[mt], bh);
                }
            }
        }
        __syncthreads();
    }

    // scatter qkv to smem; q pre-scaled by C^-0.5
    const float qscale = rsqrtf((float)CC);
#pragma unroll
    for (int mt = 0; mt < 2; ++mt)
#pragma unroll
        for (int nt = 0; nt < 6; ++nt)
#pragma unroll
            for (int e = 0; e < 4; ++e) {
                int r   = R + mt * 16 + grp + ((e >= 2) ? 8 : 0);
                int cgl = nt * 8 + 2 * tig + (e & 1);
                float v = acc[mt][nt][e];
                if (cgl < 16)      q_s[r * XPAD + cgl]        = v * qscale;
                else if (cgl < 32) k_s[r * XPAD + (cgl - 16)] = v;
                else               v_s[r * XPAD + (cgl - 32)] = v;
            }
    __syncthreads();

    // ================= Phase 2: attention with column softmax =================
    float oacc[2][2][4];
#pragma unroll
    for (int mt = 0; mt < 2; ++mt)
#pragma unroll
        for (int nt = 0; nt < 2; ++nt)
#pragma unroll
            for (int e = 0; e < 4; ++e) oacc[mt][nt][e] = 0.f;

    for (int blk = 0; blk < TT / SBLK; ++blk) {
        const int s0 = blk * SBLK;

        // ---- S block: [256 rows t] x [32 cols s], K = 16 ----
        float sf[2][4][4];
#pragma unroll
        for (int mt = 0; mt < 2; ++mt)
#pragma unroll
            for (int nt = 0; nt < 4; ++nt)
#pragma unroll
                for (int e = 0; e < 4; ++e) sf[mt][nt][e] = 0.f;

#pragma unroll
        for (int k8 = 0; k8 < 2; ++k8) {
            const int ko = k8 * 8;
            unsigned aq[2][4];
#pragma unroll
            for (int mt = 0; mt < 2; ++mt) {
                int r0 = R + mt * 16 + grp;
                aq[mt][0] = f2tf(q_s[r0 * XPAD + ko + tig]);
                aq[mt][1] = f2tf(q_s[(r0 + 8) * XPAD + ko + tig]);
                aq[mt][2] = f2tf(q_s[r0 * XPAD + ko + tig + 4]);
                aq[mt][3] = f2tf(q_s[(r0 + 8) * XPAD + ko + tig + 4]);
            }
#pragma unroll
            for (int nt = 0; nt < 4; ++nt) {
                int sc = s0 + nt * 8 + grp;
                unsigned bb[2];
                bb[0] = f2tf(k_s[sc * XPAD + ko + tig]);
                bb[1] = f2tf(k_s[sc * XPAD + ko + tig + 4]);
#pragma unroll
                for (int mt = 0; mt < 2; ++mt) mma_tf32(sf[mt][nt], aq[mt], bb);
            }
        }
        // masked store (valid iff s_global <= t)
#pragma unroll
        for (int mt = 0; mt < 2; ++mt)
#pragma unroll
            for (int nt = 0; nt < 4; ++nt)
#pragma unroll
                for (int e = 0; e < 4; ++e) {
                    int r  = R + mt * 16 + grp + ((e >= 2) ? 8 : 0);
                    int c  = nt * 8 + 2 * tig + (e & 1);
                    int sg = s0 + c;
                    s_blk[r * SPAD + c] = (sg <= r) ? sf[mt][nt][e] : -1e30f;
                }
        __syncthreads();

        // ---- column softmax over t (axis=1 of wei) ----
        {
            const int col  = tid & 31;
            const int part = tid >> 5;
            const int base = part * 32;
            float m = -1e30f;
#pragma unroll
            for (int r = 0; r < 32; ++r)
                m = fmaxf(m, s_blk[(base + r) * SPAD + col]);
            pmax[part * 32 + col] = m;
            __syncthreads();
            float cm = pmax[col];
#pragma unroll
            for (int p = 1; p < 8; ++p) cm = fmaxf(cm, pmax[p * 32 + col]);
            float ssum = 0.f;
#pragma unroll
            for (int r = 0; r < 32; ++r) {
                int idx = (base + r) * SPAD + col;
                float e = __expf(s_blk[idx] - cm);
                s_blk[idx] = e;
                ssum += e;
            }
            psum[part * 32 + col] = ssum;
            __syncthreads();
            if (tid < 32) {
                float tot = 0.f;
#pragma unroll
                for (int p = 0; p < 8; ++p) tot += psum[p * 32 + tid];
                rinv[tid] = 1.0f / tot;
            }
            __syncthreads();
        }

        // ---- PV: out += E[256,32] @ (rinv[s] * v[s0:s0+32, 16]), split-tf32 ----
#pragma unroll
        for (int k8 = 0; k8 < 4; ++k8) {
            const int ko = k8 * 8;
            unsigned ph[2][4], pl[2][4];
#pragma unroll
            for (int mt = 0; mt < 2; ++mt) {
                int r0 = R + mt * 16 + grp;
                float e0 = s_blk[r0 * SPAD + ko + tig];
                float e1 = s_blk[(r0 + 8) * SPAD + ko + tig];
                float e2 = s_blk[r0 * SPAD + ko + tig + 4];
                float e3 = s_blk[(r0 + 8) * SPAD + ko + tig + 4];
                ph[mt][0] = f2tf(e0); pl[mt][0] = f2tf(e0 - __uint_as_float(ph[mt][0]));
                ph[mt][1] = f2tf(e1); pl[mt][1] = f2tf(e1 - __uint_as_float(ph[mt][1]));
                ph[mt][2] = f2tf(e2); pl[mt][2] = f2tf(e2 - __uint_as_float(ph[mt][2]));
                ph[mt][3] = f2tf(e3); pl[mt][3] = f2tf(e3 - __uint_as_float(ph[mt][3]));
            }
#pragma unroll
            for (int nt = 0; nt < 2; ++nt) {
                int d = nt * 8 + grp;
                float vv0 = v_s[(s0 + ko + tig) * XPAD + d]     * rinv[ko + tig];
                float vv1 = v_s[(s0 + ko + tig + 4) * XPAD + d] * rinv[ko + tig + 4];
                unsigned bh[2], bl[2];
                bh[0] = f2tf(vv0); bl[0] = f2tf(vv0 - __uint_as_float(bh[0]));
                bh[1] = f2tf(vv1); bl[1] = f2tf(vv1 - __uint_as_float(bh[1]));
#pragma unroll
                for (int mt = 0; mt < 2; ++mt) {
                    mma_tf32(oacc[mt][nt], ph[mt], bh);
                    mma_tf32(oacc[mt][nt], ph[mt], bl);
                    mma_tf32(oacc[mt][nt], pl[mt], bh);
                }
            }
        }
        __syncthreads();
    }

    // ---- write out[b, t, d] ----
    float* ob = out + (size_t)b * TT * HSZ;
#pragma unroll
    for (int mt = 0; mt < 2; ++mt)
#pragma unroll
        for (int nt = 0; nt < 2; ++nt) {
            int r0 = R + mt * 16 + grp;
            int c  = nt * 8 + 2 * tig;
            *reinterpret_cast<float2*>(ob + r0 * HSZ + c) =
                make_float2(oacc[mt][nt][0], oacc[mt][nt][1]);
            *reinterpret_cast<float2*>(ob + (r0 + 8) * HSZ + c) =
                make_float2(oacc[mt][nt][2], oacc[mt][nt][3]);
        }
}

extern "C" void kernel_launch(void* const* d_in, const int* in_sizes, int n_in,
                              void* d_out, int out_size) {
    const float* x  = (const float*)d_in[0];
    const float* wk = (const float*)d_in[1];
    const float* wq = (const float*)d_in[2];
    const float* wv = (const float*)d_in[3];
    float* out      = (float*)d_out;

    const int B = in_sizes[0] / (TT * CC);  // 512

    cudaFuncSetAttribute(head_fused_kernel,
                         cudaFuncAttributeMaxDynamicSharedMemorySize, SMEM_BYTES);
    head_fused_kernel<<<B, 256, SMEM_BYTES>>>(x, wk, wq, wv, out);
}

// round 3
// speedup vs baseline: 1.8401x; 1.8401x over previous
#include <cuda_runtime.h>
#include <cstdint>

// Problem constants: B=512, T=256, C=384, HS=16
#define TT   256
#define CC   384
#define HSZ  16
#define NQKV 48
#define KCH  32          // K-chunk for projection
#define NKC  (CC/KCH)    // 12
#define XP1  36          // x tile row stride (floats), conflict-free for frag loads
#define WSP  56          // W tile row stride, conflict-free
#define QKP  20          // q/k row stride (conflict-free for grp-row pattern)
#define VPD  24          // v row stride (conflict-free for tig-row pattern)

// smem (floats):
//  phase1: 2 x (256*36 + 32*56) = 22016 f = 88064 B  (max)
//  phase2: q[256*20] k[256*20] v[256*24] psum[8*32] rinv[32] = 16672 f
#define SMEM_FLOATS (2 * (TT * XP1 + KCH * WSP))
#define SMEM_BYTES  (SMEM_FLOATS * 4)

__device__ __forceinline__ unsigned f2tf(float f) {
    unsigned r;
    asm("cvt.rna.tf32.f32 %0, %1;" : "=r"(r) : "f"(f));
    return r;
}

__device__ __forceinline__ void mma_tf32(float* c, const unsigned* a, const unsigned* b) {
    asm volatile(
        "mma.sync.aligned.m16n8k8.row.col.f32.tf32.tf32.f32 "
        "{%0,%1,%2,%3}, {%4,%5,%6,%7}, {%8,%9}, {%0,%1,%2,%3};"
        : "+f"(c[0]), "+f"(c[1]), "+f"(c[2]), "+f"(c[3])
        : "r"(a[0]), "r"(a[1]), "r"(a[2]), "r"(a[3]), "r"(b[0]), "r"(b[1]));
}

__device__ __forceinline__ void cpa16(uint32_t saddr, const float* g) {
    asm volatile("cp.async.ca.shared.global [%0], [%1], 16;" :: "r"(saddr), "l"(g));
}

__global__ void __launch_bounds__(256, 2) head_fused_kernel(
    const float* __restrict__ x,
    const float* __restrict__ wk,
    const float* __restrict__ wq,
    const float* __restrict__ wv,
    float* __restrict__ out)
{
    extern __shared__ float sm[];
    const int b    = blockIdx.x;
    const int tid  = threadIdx.x;
    const int lane = tid & 31;
    const int warp = tid >> 5;
    const int grp  = lane >> 2;  // 0..7
    const int tig  = lane & 3;   // 0..3
    const int R    = warp * 32;  // this warp's 32 rows

    const uint32_t sm_base = (uint32_t)__cvta_generic_to_shared(sm);

    // phase-2 smem views
    float* q_s  = sm;
    float* k_s  = q_s + TT * QKP;
    float* v_s  = k_s + TT * QKP;
    float* psum = v_s + TT * VPD;
    float* rinv = psum + 8 * 32;

    const float* xb = x + (size_t)b * TT * CC;

    // ================= Phase 1: qkv = x @ [Wq|Wk|Wv], split-tf32, cp.async DB =====
    float acc[2][6][4];
#pragma unroll
    for (int mt = 0; mt < 2; ++mt)
#pragma unroll
        for (int nt = 0; nt < 6; ++nt)
#pragma unroll
            for (int e = 0; e < 4; ++e) acc[mt][nt][e] = 0.f;

    auto load_chunk = [&](int kc, int buf) {
        const float* xg = xb + kc * KCH;
        uint32_t xs_a = sm_base + (uint32_t)(buf * TT * XP1) * 4u;
#pragma unroll
        for (int i = 0; i < 8; ++i) {
            int row = (tid >> 3) + i * 32;
            int c4  = (tid & 7) * 4;
            cpa16(xs_a + (uint32_t)(row * XP1 + c4) * 4u, xg + row * CC + c4);
        }
        uint32_t ws_a = sm_base + (uint32_t)(2 * TT * XP1 + buf * KCH * WSP) * 4u;
#pragma unroll
        for (int i = 0; i < 2; ++i) {
            int f = tid + i * 256;
            if (f < KCH * 12) {
                int rowk = f / 12, c4 = f % 12;
                int gk = kc * KCH + rowk;
                const float* src = (c4 < 4) ? (wq + gk * HSZ + c4 * 4)
                                 : (c4 < 8) ? (wk + gk * HSZ + (c4 - 4) * 4)
                                            : (wv + gk * HSZ + (c4 - 8) * 4);
                cpa16(ws_a + (uint32_t)(rowk * WSP + c4 * 4) * 4u, src);
            }
        }
    };

    load_chunk(0, 0);
    asm volatile("cp.async.commit_group;");

    for (int kc = 0; kc < NKC; ++kc) {
        const int buf = kc & 1;
        if (kc + 1 < NKC) {
            load_chunk(kc + 1, buf ^ 1);
            asm volatile("cp.async.commit_group;");
            asm volatile("cp.async.wait_group 1;");
        } else {
            asm volatile("cp.async.wait_group 0;");
        }
        __syncthreads();

        const float* xs = sm + buf * TT * XP1;
        const float* ws = sm + 2 * TT * XP1 + buf * KCH * WSP;

#pragma unroll
        for (int k8 = 0; k8 < 4; ++k8) {
            const int ko = k8 * 8;
            unsigned ah[2][4], al[2][4];
#pragma unroll
            for (int mt = 0; mt < 2; ++mt) {
                int r0 = R + mt * 16 + grp;
                float v0 = xs[r0 * XP1 + ko + tig];
                float v1 = xs[(r0 + 8) * XP1 + ko + tig];
                float v2 = xs[r0 * XP1 + ko + tig + 4];
                float v3 = xs[(r0 + 8) * XP1 + ko + tig + 4];
                ah[mt][0] = f2tf(v0); al[mt][0] = f2tf(v0 - __uint_as_float(ah[mt][0]));
                ah[mt][1] = f2tf(v1); al[mt][1] = f2tf(v1 - __uint_as_float(ah[mt][1]));
                ah[mt][2] = f2tf(v2); al[mt][2] = f2tf(v2 - __uint_as_float(ah[mt][2]));
                ah[mt][3] = f2tf(v3); al[mt][3] = f2tf(v3 - __uint_as_float(ah[mt][3]));
            }
#pragma unroll
            for (int nt = 0; nt < 6; ++nt) {
                int cb = nt * 8 + grp;
                float w0 = ws[(ko + tig) * WSP + cb];
                float w1 = ws[(ko + tig + 4) * WSP + cb];
                unsigned bh[2], bl[2];
                bh[0] = f2tf(w0); bl[0] = f2tf(w0 - __uint_as_float(bh[0]));
                bh[1] = f2tf(w1); bl[1] = f2tf(w1 - __uint_as_float(bh[1]));
#pragma unroll
                for (int mt = 0; mt < 2; ++mt) {
                    mma_tf32(acc[mt][nt], ah[mt], bh);
                    mma_tf32(acc[mt][nt], ah[mt], bl);
                    mma_tf32(acc[mt][nt], al[mt], bh);
                }
            }
        }
        __syncthreads();
    }

    // scatter qkv to smem; q pre-scaled by C^-0.5
    const float qscale = rsqrtf((float)CC);
#pragma unroll
    for (int mt = 0; mt < 2; ++mt)
#pragma unroll
        for (int nt = 0; nt < 6; ++nt)
#pragma unroll
            for (int e = 0; e < 4; ++e) {
                int r   = R + mt * 16 + grp + ((e >= 2) ? 8 : 0);
                int cgl = nt * 8 + 2 * tig + (e & 1);
                float v = acc[mt][nt][e];
                if (cgl < 16)      q_s[r * QKP + cgl]        = v * qscale;
                else if (cgl < 32) k_s[r * QKP + (cgl - 16)] = v;
                else               v_s[r * VPD + (cgl - 32)] = v;
            }
    __syncthreads();

    // ================= Phase 2: attention, column softmax, S in registers =========
    float oacc[2][2][4];
#pragma unroll
    for (int mt = 0; mt < 2; ++mt)
#pragma unroll
        for (int nt = 0; nt < 2; ++nt)
#pragma unroll
            for (int e = 0; e < 4; ++e) oacc[mt][nt][e] = 0.f;

    for (int blk = 0; blk < TT / 32; ++blk) {
        const int s0 = blk * 32;
        const bool active = (blk <= warp);

        float ef[2][4][4];     // exp(S) values in C-fragment layout
        float ps[4][2];        // per-column partial sums (this warp's 32 rows)
#pragma unroll
        for (int nt = 0; nt < 4; ++nt) { ps[nt][0] = 0.f; ps[nt][1] = 0.f; }

        if (active) {
            // ---- S = q k^T (K=16), single tf32 ----
#pragma unroll
            for (int mt = 0; mt < 2; ++mt)
#pragma unroll
                for (int nt = 0; nt < 4; ++nt)
#pragma unroll
                    for (int e = 0; e < 4; ++e) ef[mt][nt][e] = 0.f;
#pragma unroll
            for (int k8 = 0; k8 < 2; ++k8) {
                const int ko = k8 * 8;
                unsigned aq[2][4];
#pragma unroll
                for (int mt = 0; mt < 2; ++mt) {
                    int r0 = R + mt * 16 + grp;
                    aq[mt][0] = f2tf(q_s[r0 * QKP + ko + tig]);
                    aq[mt][1] = f2tf(q_s[(r0 + 8) * QKP + ko + tig]);
                    aq[mt][2] = f2tf(q_s[r0 * QKP + ko + tig + 4]);
                    aq[mt][3] = f2tf(q_s[(r0 + 8) * QKP + ko + tig + 4]);
                }
#pragma unroll
                for (int nt = 0; nt < 4; ++nt) {
                    int sc = s0 + nt * 8 + grp;
                    unsigned bb[2];
                    bb[0] = f2tf(k_s[sc * QKP + ko + tig]);
                    bb[1] = f2tf(k_s[sc * QKP + ko + tig + 4]);
#pragma unroll
                    for (int mt = 0; mt < 2; ++mt) mma_tf32(ef[mt][nt], aq[mt], bb);
                }
            }
            // ---- mask + exp (logits are tiny; no max subtraction needed) ----
#pragma unroll
            for (int mt = 0; mt < 2; ++mt)
#pragma unroll
                for (int nt = 0; nt < 4; ++nt)
#pragma unroll
                    for (int e = 0; e < 4; ++e) {
                        int r  = R + mt * 16 + grp + ((e >= 2) ? 8 : 0);
                        int sg = s0 + nt * 8 + 2 * tig + (e & 1);
                        ef[mt][nt][e] = (sg <= r) ? __expf(ef[mt][nt][e]) : 0.f;
                    }
            // ---- per-column partial sums over this warp's rows ----
#pragma unroll
            for (int nt = 0; nt < 4; ++nt)
#pragma unroll
                for (int bb = 0; bb < 2; ++bb) {
                    float s = ef[0][nt][bb] + ef[0][nt][bb + 2]
                            + ef[1][nt][bb] + ef[1][nt][bb + 2];
                    s += __shfl_xor_sync(0xffffffffu, s, 4);
                    s += __shfl_xor_sync(0xffffffffu, s, 8);
                    s += __shfl_xor_sync(0xffffffffu, s, 16);
                    ps[nt][bb] = s;
                }
        }
        if (grp == 0) {
#pragma unroll
            for (int nt = 0; nt < 4; ++nt) {
                psum[warp * 32 + nt * 8 + 2 * tig]     = ps[nt][0];
                psum[warp * 32 + nt * 8 + 2 * tig + 1] = ps[nt][1];
            }
        }
        __syncthreads();
        if (tid < 32) {
            float s = 0.f;
#pragma unroll
            for (int w = 0; w < 8; ++w) s += psum[w * 32 + tid];
            rinv[tid] = 1.0f / s;
        }
        __syncthreads();

        if (active) {
            // ---- PV: oacc += P[32r x 32s] @ (rinv[s] * v[s, 16]), split-tf32 ----
            const int src1 = grp * 4 + (tig >> 1);
            const int src2 = src1 + 2;
            const int sel  = tig & 1;
#pragma unroll
            for (int k8 = 0; k8 < 4; ++k8) {
                const int ko = k8 * 8;
                unsigned ph[2][4], pl[2][4];
#pragma unroll
                for (int mt = 0; mt < 2; ++mt) {
                    float s0v = __shfl_sync(0xffffffffu, ef[mt][k8][0], src1);
                    float s1v = __shfl_sync(0xffffffffu, ef[mt][k8][1], src1);
                    float s2v = __shfl_sync(0xffffffffu, ef[mt][k8][2], src1);
                    float s3v = __shfl_sync(0xffffffffu, ef[mt][k8][3], src1);
                    float t0v = __shfl_sync(0xffffffffu, ef[mt][k8][0], src2);
                    float t1v = __shfl_sync(0xffffffffu, ef[mt][k8][1], src2);
                    float t2v = __shfl_sync(0xffffffffu, ef[mt][k8][2], src2);
                    float t3v = __shfl_sync(0xffffffffu, ef[mt][k8][3], src2);
                    float a0 = sel ? s1v : s0v;   // (grp,   tig)
                    float a1 = sel ? s3v : s2v;   // (grp+8, tig)
                    float a2 = sel ? t1v : t0v;   // (grp,   tig+4)
                    float a3 = sel ? t3v : t2v;   // (grp+8, tig+4)
                    ph[mt][0] = f2tf(a0); pl[mt][0] = f2tf(a0 - __uint_as_float(ph[mt][0]));
                    ph[mt][1] = f2tf(a1); pl[mt][1] = f2tf(a1 - __uint_as_float(ph[mt][1]));
                    ph[mt][2] = f2tf(a2); pl[mt][2] = f2tf(a2 - __uint_as_float(ph[mt][2]));
                    ph[mt][3] = f2tf(a3); pl[mt][3] = f2tf(a3 - __uint_as_float(ph[mt][3]));
                }
#pragma unroll
                for (int nt = 0; nt < 2; ++nt) {
                    int d = nt * 8 + grp;
                    float vv0 = v_s[(s0 + ko + tig) * VPD + d]     * rinv[ko + tig];
                    float vv1 = v_s[(s0 + ko + tig + 4) * VPD + d] * rinv[ko + tig + 4];
                    unsigned bh[2], bl[2];
                    bh[0] = f2tf(vv0); bl[0] = f2tf(vv0 - __uint_as_float(bh[0]));
                    bh[1] = f2tf(vv1); bl[1] = f2tf(vv1 - __uint_as_float(bh[1]));
#pragma unroll
                    for (int mt = 0; mt < 2; ++mt) {
                        mma_tf32(oacc[mt][nt], ph[mt], bh);
                        mma_tf32(oacc[mt][nt], ph[mt], bl);
                        mma_tf32(oacc[mt][nt], pl[mt], bh);
                    }
                }
            }
        }
        __syncthreads();
    }

    // ---- write out[b, t, d] ----
    float* ob = out + (size_t)b * TT * HSZ;
#pragma unroll
    for (int mt = 0; mt < 2; ++mt)
#pragma unroll
        for (int nt = 0; nt < 2; ++nt) {
            int r0 = R + mt * 16 + grp;
            int c  = nt * 8 + 2 * tig;
            *reinterpret_cast<float2*>(ob + r0 * HSZ + c) =
                make_float2(oacc[mt][nt][0], oacc[mt][nt][1]);
            *reinterpret_cast<float2*>(ob + (r0 + 8) * HSZ + c) =
                make_float2(oacc[mt][nt][2], oacc[mt][nt][3]);
        }
}

extern "C" void kernel_launch(void* const* d_in, const int* in_sizes, int n_in,
                              void* d_out, int out_size) {
    const float* x  = (const float*)d_in[0];
    const float* wk = (const float*)d_in[1];
    const float* wq = (const float*)d_in[2];
    const float* wv = (const float*)d_in[3];
    float* out      = (float*)d_out;

    const int B = in_sizes[0] / (TT * CC);  // 512

    cudaFuncSetAttribute(head_fused_kernel,
                         cudaFuncAttributeMaxDynamicSharedMemorySize, SMEM_BYTES);
    head_fused_kernel<<<B, 256, SMEM_BYTES>>>(x, wk, wq, wv, out);
}

// round 4
// speedup vs baseline: 2.2920x; 1.2456x over previous
#include <cuda_runtime.h>
#include <cstdint>

// Problem constants: B=512, T=256, C=384, HS=16
#define TT   256
#define CC   384
#define HSZ  16
#define NQKV 48
#define KCH  32          // K-chunk for projection
#define NKC  (CC/KCH)    // 12
#define XP1  36          // x tile row stride (floats)
#define WSP  56          // W tile row stride
#define QKP  20          // q/k row stride
#define VPD  24          // v row stride

// smem (floats):
//  phase1: 2 x (256*36 + 32*56) = 22016 f = 88064 B  (max)
//  phase2: q[256*20] k[256*20] v[256*24] psum[8*32] rinv[32] = 16672 f
#define SMEM_FLOATS (2 * (TT * XP1 + KCH * WSP))
#define SMEM_BYTES  (SMEM_FLOATS * 4)

__device__ __forceinline__ unsigned f2tf(float f) {
    unsigned r;
    asm("cvt.rna.tf32.f32 %0, %1;" : "=r"(r) : "f"(f));
    return r;
}

__device__ __forceinline__ void mma_tf32(float* c, const unsigned* a, const unsigned* b) {
    asm volatile(
        "mma.sync.aligned.m16n8k8.row.col.f32.tf32.tf32.f32 "
        "{%0,%1,%2,%3}, {%4,%5,%6,%7}, {%8,%9}, {%0,%1,%2,%3};"
        : "+f"(c[0]), "+f"(c[1]), "+f"(c[2]), "+f"(c[3])
        : "r"(a[0]), "r"(a[1]), "r"(a[2]), "r"(a[3]), "r"(b[0]), "r"(b[1]));
}

__device__ __forceinline__ void cpa16(uint32_t saddr, const float* g) {
    asm volatile("cp.async.ca.shared.global [%0], [%1], 16;" :: "r"(saddr), "l"(g));
}

__global__ void __launch_bounds__(256, 2) head_fused_kernel(
    const float* __restrict__ x,
    const float* __restrict__ wk,
    const float* __restrict__ wq,
    const float* __restrict__ wv,
    float* __restrict__ out)
{
    extern __shared__ float sm[];
    const int b    = blockIdx.x;
    const int tid  = threadIdx.x;
    const int lane = tid & 31;
    const int warp = tid >> 5;
    const int grp  = lane >> 2;  // 0..7
    const int tig  = lane & 3;   // 0..3

    const uint32_t sm_base = (uint32_t)__cvta_generic_to_shared(sm);

    // phase-2 smem views
    float* q_s  = sm;
    float* k_s  = q_s + TT * QKP;
    float* v_s  = k_s + TT * QKP;
    float* psum = v_s + TT * VPD;
    float* rinv = psum + 8 * 32;

    const float* xb = x + (size_t)b * TT * CC;

    // ================= Phase 1: qkv = x @ [Wq|Wk|Wv] =================
    // split-tf32 on x only (2-term: xh*w + xl*w), W single tf32. cp.async DB.
    const int R = warp * 32;   // phase-1 row base (dense, any mapping ok)

    float acc[2][6][4];
#pragma unroll
    for (int mt = 0; mt < 2; ++mt)
#pragma unroll
        for (int nt = 0; nt < 6; ++nt)
#pragma unroll
            for (int e = 0; e < 4; ++e) acc[mt][nt][e] = 0.f;

    auto load_chunk = [&](int kc, int buf) {
        const float* xg = xb + kc * KCH;
        uint32_t xs_a = sm_base + (uint32_t)(buf * TT * XP1) * 4u;
#pragma unroll
        for (int i = 0; i < 8; ++i) {
            int row = (tid >> 3) + i * 32;
            int c4  = (tid & 7) * 4;
            cpa16(xs_a + (uint32_t)(row * XP1 + c4) * 4u, xg + row * CC + c4);
        }
        uint32_t ws_a = sm_base + (uint32_t)(2 * TT * XP1 + buf * KCH * WSP) * 4u;
#pragma unroll
        for (int i = 0; i < 2; ++i) {
            int f = tid + i * 256;
            if (f < KCH * 12) {
                int rowk = f / 12, c4 = f % 12;
                int gk = kc * KCH + rowk;
                const float* src = (c4 < 4) ? (wq + gk * HSZ + c4 * 4)
                                 : (c4 < 8) ? (wk + gk * HSZ + (c4 - 4) * 4)
                                            : (wv + gk * HSZ + (c4 - 8) * 4);
                cpa16(ws_a + (uint32_t)(rowk * WSP + c4 * 4) * 4u, src);
            }
        }
    };

    load_chunk(0, 0);
    asm volatile("cp.async.commit_group;");

    for (int kc = 0; kc < NKC; ++kc) {
        const int buf = kc & 1;
        if (kc + 1 < NKC) {
            load_chunk(kc + 1, buf ^ 1);
            asm volatile("cp.async.commit_group;");
            asm volatile("cp.async.wait_group 1;");
        } else {
            asm volatile("cp.async.wait_group 0;");
        }
        __syncthreads();

        const float* xs = sm + buf * TT * XP1;
        const float* ws = sm + 2 * TT * XP1 + buf * KCH * WSP;

#pragma unroll
        for (int k8 = 0; k8 < 4; ++k8) {
            const int ko = k8 * 8;
            unsigned ah[2][4], al[2][4];
#pragma unroll
            for (int mt = 0; mt < 2; ++mt) {
                int r0 = R + mt * 16 + grp;
                float v0 = xs[r0 * XP1 + ko + tig];
                float v1 = xs[(r0 + 8) * XP1 + ko + tig];
                float v2 = xs[r0 * XP1 + ko + tig + 4];
                float v3 = xs[(r0 + 8) * XP1 + ko + tig + 4];
                ah[mt][0] = f2tf(v0); al[mt][0] = f2tf(v0 - __uint_as_float(ah[mt][0]));
                ah[mt][1] = f2tf(v1); al[mt][1] = f2tf(v1 - __uint_as_float(ah[mt][1]));
                ah[mt][2] = f2tf(v2); al[mt][2] = f2tf(v2 - __uint_as_float(ah[mt][2]));
                ah[mt][3] = f2tf(v3); al[mt][3] = f2tf(v3 - __uint_as_float(ah[mt][3]));
            }
#pragma unroll
            for (int nt = 0; nt < 6; ++nt) {
                int cb = nt * 8 + grp;
                unsigned bh[2];
                bh[0] = f2tf(ws[(ko + tig) * WSP + cb]);
                bh[1] = f2tf(ws[(ko + tig + 4) * WSP + cb]);
#pragma unroll
                for (int mt = 0; mt < 2; ++mt) {
                    mma_tf32(acc[mt][nt], ah[mt], bh);
                    mma_tf32(acc[mt][nt], al[mt], bh);
                }
            }
        }
        __syncthreads();
    }

    // scatter qkv to smem; q pre-scaled by C^-0.5
    const float qscale = rsqrtf((float)CC);
#pragma unroll
    for (int mt = 0; mt < 2; ++mt)
#pragma unroll
        for (int nt = 0; nt < 6; ++nt)
#pragma unroll
            for (int e = 0; e < 4; ++e) {
                int r   = R + mt * 16 + grp + ((e >= 2) ? 8 : 0);
                int cgl = nt * 8 + 2 * tig + (e & 1);
                float v = acc[mt][nt][e];
                if (cgl < 16)      q_s[r * QKP + cgl]        = v * qscale;
                else if (cgl < 32) k_s[r * QKP + (cgl - 16)] = v;
                else               v_s[r * VPD + (cgl - 32)] = v;
            }
    __syncthreads();

    // ================= Phase 2: attention, column softmax, balanced triangle ======
    // Warp owns 16-row strips {warp, 15-warp}: every warp gets 9 strip-block units.
    const int rb0 = warp * 16;          // strip A rows
    const int rb1 = 240 - warp * 16;    // strip B rows
    int rb[2] = {rb0, rb1};

    float oacc[2][2][4];
#pragma unroll
    for (int mt = 0; mt < 2; ++mt)
#pragma unroll
        for (int nt = 0; nt < 2; ++nt)
#pragma unroll
            for (int e = 0; e < 4; ++e) oacc[mt][nt][e] = 0.f;

    for (int blk = 0; blk < TT / 32; ++blk) {
        const int s0 = blk * 32;
        const bool act0 = (warp >= 2 * blk);        // strip A has unmasked rows
        const bool act1 = ((15 - warp) >= 2 * blk); // strip B (act0 implies act1)
        const bool anyact = act1;

        float ef[2][4][4];     // exp(S) in C-fragment layout (zeros if inactive)
#pragma unroll
        for (int mt = 0; mt < 2; ++mt)
#pragma unroll
            for (int nt = 0; nt < 4; ++nt)
#pragma unroll
                for (int e = 0; e < 4; ++e) ef[mt][nt][e] = 0.f;

        float ps[4][2];
#pragma unroll
        for (int nt = 0; nt < 4; ++nt) { ps[nt][0] = 0.f; ps[nt][1] = 0.f; }

        if (anyact) {
            // ---- S = q k^T (K=16), single tf32, per active strip ----
#pragma unroll
            for (int k8 = 0; k8 < 2; ++k8) {
                const int ko = k8 * 8;
                unsigned aq[2][4];
#pragma unroll
                for (int mt = 0; mt < 2; ++mt) {
                    if (mt == 0 && !act0) continue;
                    int r0 = rb[mt] + grp;
                    aq[mt][0] = f2tf(q_s[r0 * QKP + ko + tig]);
                    aq[mt][1] = f2tf(q_s[(r0 + 8) * QKP + ko + tig]);
                    aq[mt][2] = f2tf(q_s[r0 * QKP + ko + tig + 4]);
                    aq[mt][3] = f2tf(q_s[(r0 + 8) * QKP + ko + tig + 4]);
                }
#pragma unroll
                for (int nt = 0; nt < 4; ++nt) {
                    int sc = s0 + nt * 8 + grp;
                    unsigned bb[2];
                    bb[0] = f2tf(k_s[sc * QKP + ko + tig]);
                    bb[1] = f2tf(k_s[sc * QKP + ko + tig + 4]);
                    if (act0) mma_tf32(ef[0][nt], aq[0], bb);
                    mma_tf32(ef[1][nt], aq[1], bb);
                }
            }
            // ---- mask + exp (logits tiny; no max subtraction) ----
#pragma unroll
            for (int mt = 0; mt < 2; ++mt) {
                if (mt == 0 && !act0) {
#pragma unroll
                    for (int nt = 0; nt < 4; ++nt)
#pragma unroll
                        for (int e = 0; e < 4; ++e) ef[0][nt][e] = 0.f;
                    continue;
                }
#pragma unroll
                for (int nt = 0; nt < 4; ++nt)
#pragma unroll
                    for (int e = 0; e < 4; ++e) {
                        int r  = rb[mt] + grp + ((e >= 2) ? 8 : 0);
                        int sg = s0 + nt * 8 + 2 * tig + (e & 1);
                        ef[mt][nt][e] = (sg <= r) ? __expf(ef[mt][nt][e]) : 0.f;
                    }
            }
            // ---- per-column partial sums over this warp's 32 rows ----
#pragma unroll
            for (int nt = 0; nt < 4; ++nt)
#pragma unroll
                for (int bb2 = 0; bb2 < 2; ++bb2) {
                    float s = ef[0][nt][bb2] + ef[0][nt][bb2 + 2]
                            + ef[1][nt][bb2] + ef[1][nt][bb2 + 2];
                    s += __shfl_xor_sync(0xffffffffu, s, 4);
                    s += __shfl_xor_sync(0xffffffffu, s, 8);
                    s += __shfl_xor_sync(0xffffffffu, s, 16);
                    ps[nt][bb2] = s;
                }
        }
        if (grp == 0) {
#pragma unroll
            for (int nt = 0; nt < 4; ++nt) {
                psum[warp * 32 + nt * 8 + 2 * tig]     = ps[nt][0];
                psum[warp * 32 + nt * 8 + 2 * tig + 1] = ps[nt][1];
            }
        }
        __syncthreads();
        if (tid < 32) {
            float s = 0.f;
#pragma unroll
            for (int w = 0; w < 8; ++w) s += psum[w * 32 + tid];
            rinv[tid] = 1.0f / s;
        }
        __syncthreads();

        if (anyact) {
            // ---- PV: oacc += P @ (rinv[s]*v), P single tf32, v split (2-term) ----
            const int src1 = grp * 4 + (tig >> 1);
            const int src2 = src1 + 2;
            const int sel  = tig & 1;
#pragma unroll
            for (int k8 = 0; k8 < 4; ++k8) {
                const int ko = k8 * 8;
                unsigned ph[2][4];
#pragma unroll
                for (int mt = 0; mt < 2; ++mt) {
                    if (mt == 0 && !act0) continue;
                    float s0v = __shfl_sync(0xffffffffu, ef[mt][k8][0], src1);
                    float s1v = __shfl_sync(0xffffffffu, ef[mt][k8][1], src1);
                    float s2v = __shfl_sync(0xffffffffu, ef[mt][k8][2], src1);
                    float s3v = __shfl_sync(0xffffffffu, ef[mt][k8][3], src1);
                    float t0v = __shfl_sync(0xffffffffu, ef[mt][k8][0], src2);
                    float t1v = __shfl_sync(0xffffffffu, ef[mt][k8][1], src2);
                    float t2v = __shfl_sync(0xffffffffu, ef[mt][k8][2], src2);
                    float t3v = __shfl_sync(0xffffffffu, ef[mt][k8][3], src2);
                    ph[mt][0] = f2tf(sel ? s1v : s0v);   // (grp,   tig)
                    ph[mt][1] = f2tf(sel ? s3v : s2v);   // (grp+8, tig)
                    ph[mt][2] = f2tf(sel ? t1v : t0v);   // (grp,   tig+4)
                    ph[mt][3] = f2tf(sel ? t3v : t2v);   // (grp+8, tig+4)
                }
#pragma unroll
                for (int nt = 0; nt < 2; ++nt) {
                    int d = nt * 8 + grp;
                    float vv0 = v_s[(s0 + ko + tig) * VPD + d]     * rinv[ko + tig];
                    float vv1 = v_s[(s0 + ko + tig + 4) * VPD + d] * rinv[ko + tig + 4];
                    unsigned bh[2], bl[2];
                    bh[0] = f2tf(vv0); bl[0] = f2tf(vv0 - __uint_as_float(bh[0]));
                    bh[1] = f2tf(vv1); bl[1] = f2tf(vv1 - __uint_as_float(bh[1]));
                    if (act0) {
                        mma_tf32(oacc[0][nt], ph[0], bh);
                        mma_tf32(oacc[0][nt], ph[0], bl);
                    }
                    mma_tf32(oacc[1][nt], ph[1], bh);
                    mma_tf32(oacc[1][nt], ph[1], bl);
                }
            }
        }
        // no trailing sync needed: next psum store only touches this warp's slot,
        // and the next rinv compute is gated by the next __syncthreads pair.
    }

    // ---- write out[b, t, d] ----
    float* ob = out + (size_t)b * TT * HSZ;
#pragma unroll
    for (int mt = 0; mt < 2; ++mt)
#pragma unroll
        for (int nt = 0; nt < 2; ++nt) {
            int r0 = rb[mt] + grp;
            int c  = nt * 8 + 2 * tig;
            *reinterpret_cast<float2*>(ob + r0 * HSZ + c) =
                make_float2(oacc[mt][nt][0], oacc[mt][nt][1]);
            *reinterpret_cast<float2*>(ob + (r0 + 8) * HSZ + c) =
                make_float2(oacc[mt][nt][2], oacc[mt][nt][3]);
        }
}

extern "C" void kernel_launch(void* const* d_in, const int* in_sizes, int n_in,
                              void* d_out, int out_size) {
    const float* x  = (const float*)d_in[0];
    const float* wk = (const float*)d_in[1];
    const float* wq = (const float*)d_in[2];
    const float* wv = (const float*)d_in[3];
    float* out      = (float*)d_out;

    const int B = in_sizes[0] / (TT * CC);  // 512

    cudaFuncSetAttribute(head_fused_kernel,
                         cudaFuncAttributeMaxDynamicSharedMemorySize, SMEM_BYTES);
    head_fused_kernel<<<B, 256, SMEM_BYTES>>>(x, wk, wq, wv, out);
}